// round 1
// baseline (speedup 1.0000x reference)
#include <cuda_runtime.h>
#include <cuda_bf16.h>
#include <math.h>

// Problem constants
#define C_    21
#define D_    2048
#define N_    512
#define NS_   256
#define H1_   1024
#define DIN_  (D_ + C_)   // 2069
#define HW_   49

// ---------------- scratch (static device memory; no allocs allowed) ----------------
__device__ float g_op[N_ * DIN_];        // pooled features ++ logits  [512, 2069]
__device__ float g_maxlogit[N_];
__device__ int   g_maxcls[N_];
__device__ float g_protos[2 * C_ * D_];  // dom0 = src (s_protos), dom1 = tgt (t_protos)
__device__ float g_bwl[C_ * D_];
__device__ float g_counts[C_];
__device__ float g_norms[3 * C_];        // [0]=t, [1]=s, [2]=bwl
__device__ float g_diff[400];
__device__ float g_bufA[N_ * H1_];
__device__ float g_bufB[N_ * H1_];
__device__ float g_z[N_];

// ---------------- helpers ----------------
__device__ __forceinline__ float block_reduce_256(float v, float* sh) {
    int t = threadIdx.x;
    sh[t] = v; __syncthreads();
    #pragma unroll
    for (int s = 128; s > 0; s >>= 1) {
        if (t < s) sh[t] += sh[t + s];
        __syncthreads();
    }
    float r = sh[0]; __syncthreads();
    return r;
}

// ---------------- 1. pooling: mean over 7x7, scatter into g_op [n*2069 + d] ----------------
__global__ void pool_kernel(const float* __restrict__ x) {
    int lane = threadIdx.x & 31;
    int warpId = (blockIdx.x * blockDim.x + threadIdx.x) >> 5;
    int nWarps = (gridDim.x * blockDim.x) >> 5;
    const int ROWS = N_ * D_;
    for (int row = warpId; row < ROWS; row += nWarps) {
        int base = row * HW_;
        float s = x[base + lane];
        if (lane + 32 < HW_) s += x[base + lane + 32];
        #pragma unroll
        for (int o = 16; o > 0; o >>= 1) s += __shfl_down_sync(0xffffffffu, s, o);
        if (lane == 0) {
            int n = row >> 11;
            int d = row & (D_ - 1);
            g_op[n * DIN_ + d] = s * (1.0f / 49.0f);
        }
    }
}

// ---------------- 2. append class_logits to g_op ----------------
__global__ void copy_logits_kernel(const float* __restrict__ logits) {
    int t = blockIdx.x * blockDim.x + threadIdx.x;
    if (t < N_ * C_) {
        int n = t / C_, c = t % C_;
        g_op[n * DIN_ + D_ + c] = logits[t];
    }
}

// ---------------- 3. softmax max prob + argmax per sample ----------------
__global__ void softmax_kernel(const float* __restrict__ logits) {
    int i = blockIdx.x * blockDim.x + threadIdx.x;
    if (i >= N_) return;
    const float* l = logits + i * C_;
    float m = -INFINITY; int am = 0;
    #pragma unroll
    for (int c = 0; c < C_; c++) { float v = l[c]; if (v > m) { m = v; am = c; } }
    float s = 0.f;
    #pragma unroll
    for (int c = 0; c < C_; c++) s += expf(l[c] - m);
    g_maxlogit[i] = 1.0f / s;   // exp(m-m)/sum = max softmax prob
    g_maxcls[i] = am;
}

// ---------------- 4. prototype scan (42 blocks: dom x class) ----------------
__global__ void proto_kernel() {
    int dom = blockIdx.x / C_;   // 0=src, 1=tgt
    int cls = blockIdx.x % C_;
    __shared__ int s_idx[NS_];
    __shared__ int s_m;
    if (threadIdx.x == 0) {
        float thr = 0.1f; int m = 0;
        int base = dom * NS_;
        for (int i = 0; i < NS_; i++) {
            int smp = base + i;
            if (g_maxcls[smp] == cls) {
                float ml = g_maxlogit[smp];
                if (ml >= thr) {
                    thr = thr * 0.5f + ml * 0.5f;  // MOM=0.5
                    s_idx[m++] = smp;
                }
            }
        }
        s_m = m;
    }
    __syncthreads();
    int m = s_m;
    float* pout = g_protos + (dom * C_ + cls) * D_;
    for (int d = threadIdx.x; d < D_; d += blockDim.x) {
        float p = 0.f;
        for (int j = 0; j < m; j++) {
            p = (p + g_op[s_idx[j] * DIN_ + d]) / (float)(j + 1);
        }
        pout[d] = p;
    }
}

// ---------------- 5. per-class mean of src features by labels ----------------
__global__ void bwl_kernel(const int* __restrict__ labels) {
    int cls = blockIdx.x;
    __shared__ int s_idx[NS_];
    __shared__ int s_m;
    if (threadIdx.x == 0) {
        int m = 0;
        for (int i = 0; i < NS_; i++) if (labels[i] == cls) s_idx[m++] = i;
        s_m = m;
        g_counts[cls] = (float)m;
    }
    __syncthreads();
    int m = s_m;
    float* out = g_bwl + cls * D_;
    for (int d = threadIdx.x; d < D_; d += blockDim.x) {
        float s = 0.f;
        for (int j = 0; j < m; j++) s += g_op[s_idx[j] * DIN_ + d];
        out[d] = (m > 0) ? (s / (float)m) : 0.f;
    }
}

// ---------------- 6. row norms (63 blocks: 3 matrices x 21 rows) ----------------
__global__ void norms_kernel() {
    __shared__ float sh[256];
    int mat = blockIdx.x / C_;
    int r = blockIdx.x % C_;
    const float* p;
    if (mat == 0)      p = g_protos + (C_ + r) * D_;  // t (dom 1)
    else if (mat == 1) p = g_protos + r * D_;          // s (dom 0)
    else               p = g_bwl + r * D_;
    float s = 0.f;
    for (int d = threadIdx.x; d < D_; d += 256) { float v = p[d]; s += v * v; }
    s = block_reduce_256(s, sh);
    if (threadIdx.x == 0) g_norms[mat * C_ + r] = fmaxf(sqrtf(s), 1e-8f);
}

// ---------------- 7. cos maps + masked abs diff ----------------
__global__ void diff_kernel() {
    __shared__ float sh[256];
    int i = blockIdx.x / 20 + 1;   // t row class
    int j = blockIdx.x % 20 + 1;   // col class
    const float* t = g_protos + (C_ + i) * D_;
    const float* s = g_protos + j * D_;
    const float* b = g_bwl + j * D_;
    float d1 = 0.f, d2 = 0.f;
    for (int d = threadIdx.x; d < D_; d += 256) {
        float tv = t[d];
        d1 += tv * s[d];
        d2 += tv * b[d];
    }
    d1 = block_reduce_256(d1, sh);
    d2 = block_reduce_256(d2, sh);
    if (threadIdx.x == 0) {
        float nt = g_norms[0 * C_ + i];
        float ns = g_norms[1 * C_ + j];
        float nb = g_norms[2 * C_ + j];
        float ptm = d1 / (nt * ns);
        float bw  = d2 / (nt * nb);
        float mask = (g_counts[i] > 0.f) ? 1.f : 0.f;
        g_diff[blockIdx.x] = fabsf(bw - ptm) * mask;
    }
}

// ---------------- 8. SGEMM 64x64x16, 256 threads, 4x4 microtile ----------------
#define BM 64
#define BN 64
#define BKK 16
__global__ void sgemm_kernel(const float* __restrict__ A, const float* __restrict__ B,
                             float* __restrict__ C, int M, int N, int K) {
    __shared__ float As[BKK][BM];
    __shared__ float Bs[BKK][BN];
    int tid = threadIdx.x;
    int tx = tid & 15, ty = tid >> 4;
    const float* Ab = A + blockIdx.y * BM * K;
    const float* Bb = B + blockIdx.x * BN;
    float acc[4][4] = {};
    for (int k0 = 0; k0 < K; k0 += BKK) {
        #pragma unroll
        for (int r = 0; r < 4; r++) {
            int idx = tid + r * 256;
            int m = idx / BKK, kk = idx % BKK;
            As[kk][m] = (k0 + kk < K) ? Ab[m * K + k0 + kk] : 0.f;
        }
        #pragma unroll
        for (int r = 0; r < 4; r++) {
            int idx = tid + r * 256;
            int kk = idx / BN, n = idx % BN;
            Bs[kk][n] = (k0 + kk < K) ? Bb[(k0 + kk) * N + n] : 0.f;
        }
        __syncthreads();
        #pragma unroll
        for (int kk = 0; kk < BKK; kk++) {
            float a[4], b[4];
            #pragma unroll
            for (int ii = 0; ii < 4; ii++) a[ii] = As[kk][ty * 4 + ii];
            #pragma unroll
            for (int jj = 0; jj < 4; jj++) b[jj] = Bs[kk][tx * 4 + jj];
            #pragma unroll
            for (int ii = 0; ii < 4; ii++)
                #pragma unroll
                for (int jj = 0; jj < 4; jj++)
                    acc[ii][jj] += a[ii] * b[jj];
        }
        __syncthreads();
    }
    float* Cb = C + (blockIdx.y * BM) * N + blockIdx.x * BN;
    #pragma unroll
    for (int ii = 0; ii < 4; ii++)
        #pragma unroll
        for (int jj = 0; jj < 4; jj++)
            Cb[(ty * 4 + ii) * N + tx * 4 + jj] = acc[ii][jj];
}

// ---------------- 9. bias + layernorm + relu, in place, rows of 1024 ----------------
__global__ void ln_relu_kernel(float* __restrict__ h, const float* __restrict__ bias) {
    __shared__ float sh[256];
    int row = blockIdx.x;
    float* p = h + row * H1_;
    float vals[4];
    float s = 0.f;
    #pragma unroll
    for (int k = 0; k < 4; k++) {
        int c = threadIdx.x + k * 256;
        vals[k] = p[c] + bias[c];
        s += vals[k];
    }
    float tot = block_reduce_256(s, sh);
    float mu = tot * (1.0f / H1_);
    float v = 0.f;
    #pragma unroll
    for (int k = 0; k < 4; k++) { float dd = vals[k] - mu; v += dd * dd; }
    float vtot = block_reduce_256(v, sh);
    float inv = rsqrtf(vtot * (1.0f / H1_) + 1e-5f);
    #pragma unroll
    for (int k = 0; k < 4; k++) {
        int c = threadIdx.x + k * 256;
        float o = (vals[k] - mu) * inv;
        p[c] = o > 0.f ? o : 0.f;
    }
}

// ---------------- 10. gemv h @ Wd + bd ----------------
__global__ void gemv_kernel(const float* __restrict__ h, const float* __restrict__ Wd,
                            const float* __restrict__ bd) {
    __shared__ float sh[256];
    int row = blockIdx.x;
    float s = 0.f;
    for (int c = threadIdx.x; c < H1_; c += 256) s += h[row * H1_ + c] * Wd[c];
    s = block_reduce_256(s, sh);
    if (threadIdx.x == 0) g_z[row] = s + bd[0];
}

// ---------------- 11. final reductions -> d_out[2] ----------------
__global__ void final_kernel(const int* __restrict__ dlabels, float* __restrict__ out) {
    __shared__ float red[512];
    int t = threadIdx.x;
    // loss_ea
    float p = 1.f / (1.f + expf(-g_z[t]));
    float y = (float)dlabels[t];
    float v = fmaxf(p, 0.f) - p * y + log1pf(expf(-fabsf(p)));
    red[t] = v; __syncthreads();
    #pragma unroll
    for (int s = 256; s > 0; s >>= 1) { if (t < s) red[t] += red[t + s]; __syncthreads(); }
    float loss_ea = red[0] * (1.0f / N_);
    __syncthreads();
    // diff sum
    red[t] = (t < 400) ? g_diff[t] : 0.f; __syncthreads();
    #pragma unroll
    for (int s = 256; s > 0; s >>= 1) { if (t < s) red[t] += red[t + s]; __syncthreads(); }
    float dsum = red[0];
    __syncthreads();
    // mask sum
    red[t] = (t >= 1 && t < C_) ? ((g_counts[t] > 0.f) ? 1.f : 0.f) : 0.f; __syncthreads();
    #pragma unroll
    for (int s = 256; s > 0; s >>= 1) { if (t < s) red[t] += red[t + s]; __syncthreads(); }
    if (t == 0) {
        float msum = red[0];
        out[0] = 1.0f * dsum / (msum * (float)(C_ - 1));  // MGRM_W = 1.0
        out[1] = loss_ea;
    }
}

// ---------------- launch ----------------
extern "C" void kernel_launch(void* const* d_in, const int* in_sizes, int n_in,
                              void* d_out, int out_size) {
    const float* ins_features  = (const float*)d_in[0];
    const float* class_logits  = (const float*)d_in[1];
    const float* W1 = (const float*)d_in[2];
    const float* b1 = (const float*)d_in[3];
    const float* W2 = (const float*)d_in[4];
    const float* b2 = (const float*)d_in[5];
    const float* W3 = (const float*)d_in[6];
    const float* b3 = (const float*)d_in[7];
    const float* Wd = (const float*)d_in[8];
    const float* bd = (const float*)d_in[9];
    const int* labels        = (const int*)d_in[10];
    const int* domain_labels = (const int*)d_in[11];
    float* out = (float*)d_out;

    float* op   = nullptr; cudaGetSymbolAddress((void**)&op, g_op);
    float* bufA = nullptr; cudaGetSymbolAddress((void**)&bufA, g_bufA);
    float* bufB = nullptr; cudaGetSymbolAddress((void**)&bufB, g_bufB);

    // pooled features + logits into op
    pool_kernel<<<8192, 256>>>(ins_features);
    copy_logits_kernel<<<(N_ * C_ + 255) / 256, 256>>>(class_logits);
    softmax_kernel<<<2, 256>>>(class_logits);
    proto_kernel<<<2 * C_, 256>>>();
    bwl_kernel<<<C_, 256>>>(labels);
    norms_kernel<<<3 * C_, 256>>>();
    diff_kernel<<<400, 256>>>();

    // MLP
    dim3 g1(H1_ / BN, N_ / BM);
    sgemm_kernel<<<g1, 256>>>(op, W1, bufA, N_, H1_, DIN_);
    ln_relu_kernel<<<N_, 256>>>(bufA, b1);
    sgemm_kernel<<<g1, 256>>>(bufA, W2, bufB, N_, H1_, H1_);
    ln_relu_kernel<<<N_, 256>>>(bufB, b2);
    sgemm_kernel<<<g1, 256>>>(bufB, W3, bufA, N_, H1_, H1_);
    ln_relu_kernel<<<N_, 256>>>(bufA, b3);
    gemv_kernel<<<N_, 256>>>(bufA, Wd, bd);

    final_kernel<<<1, 512>>>(domain_labels, out);
}

// round 4
// speedup vs baseline: 2.5673x; 2.5673x over previous
#include <cuda_runtime.h>
#include <cuda_bf16.h>
#include <math.h>
#include <stdint.h>

// Problem constants
#define C_    21
#define D_    2048
#define N_    512
#define NS_   256
#define H1_   1024
#define DIN_  (D_ + C_)   // 2069
#define S_OP  2072        // padded stride for g_op (16B-aligned rows)
#define HW_   49

// ---------------- scratch (static device memory) ----------------
__device__ float g_op[N_ * S_OP];        // pooled features ++ logits ++ zero pad
__device__ float g_maxlogit[N_];
__device__ int   g_maxcls[N_];
__device__ float g_protos[2 * C_ * D_];  // dom0 = src, dom1 = tgt
__device__ float g_bwl[C_ * D_];
__device__ float g_counts[C_];
__device__ float g_norms[3 * C_];
__device__ float g_diff[400];
__device__ float g_bufA[N_ * H1_];
__device__ float g_bufB[N_ * H1_];
__device__ float g_part[4 * N_ * H1_];   // split-K partials
__device__ float g_z[N_];
// proto/bwl prep
__device__ int   g_pidx[42 * NS_];
__device__ float g_pw[42 * NS_];
__device__ int   g_pm[42];
__device__ int   g_lidx[C_ * NS_];
__device__ int   g_lm[C_];

// ---------------- helpers ----------------
__device__ __forceinline__ float block_reduce_256(float v, float* sh) {
    int t = threadIdx.x;
    sh[t] = v; __syncthreads();
    #pragma unroll
    for (int s = 128; s > 0; s >>= 1) {
        if (t < s) sh[t] += sh[t + s];
        __syncthreads();
    }
    float r = sh[0]; __syncthreads();
    return r;
}

__device__ __forceinline__ void cp_async16(void* dst, const void* src, bool pred) {
    unsigned d = (unsigned)__cvta_generic_to_shared(dst);
    int sz = pred ? 16 : 0;
    asm volatile("cp.async.cg.shared.global [%0], [%1], 16, %2;\n"
                 :: "r"(d), "l"(src), "r"(sz));
}
__device__ __forceinline__ void cp_commit() { asm volatile("cp.async.commit_group;\n"); }
template<int Np> __device__ __forceinline__ void cp_wait() {
    asm volatile("cp.async.wait_group %0;\n" :: "n"(Np));
}

__device__ __forceinline__ void mma_tf32(float* d, const uint32_t* a, const uint32_t* b) {
    asm volatile(
        "mma.sync.aligned.m16n8k8.row.col.f32.tf32.tf32.f32 "
        "{%0,%1,%2,%3}, {%4,%5,%6,%7}, {%8,%9}, {%0,%1,%2,%3};\n"
        : "+f"(d[0]), "+f"(d[1]), "+f"(d[2]), "+f"(d[3])
        : "r"(a[0]), "r"(a[1]), "r"(a[2]), "r"(a[3]), "r"(b[0]), "r"(b[1]));
}

// ---------------- 1. pooling ----------------
__global__ void pool_kernel(const float* __restrict__ x) {
    int lane = threadIdx.x & 31;
    int warpId = (blockIdx.x * blockDim.x + threadIdx.x) >> 5;
    int nWarps = (gridDim.x * blockDim.x) >> 5;
    const int ROWS = N_ * D_;
    for (int row = warpId; row < ROWS; row += nWarps) {
        int base = row * HW_;
        float s = x[base + lane];
        if (lane + 32 < HW_) s += x[base + lane + 32];
        #pragma unroll
        for (int o = 16; o > 0; o >>= 1) s += __shfl_down_sync(0xffffffffu, s, o);
        if (lane == 0) {
            int n = row >> 11;
            int d = row & (D_ - 1);
            g_op[n * S_OP + d] = s * (1.0f / 49.0f);
        }
    }
}

// ---------------- 2. logits + zero pad ----------------
__global__ void copy_logits_kernel(const float* __restrict__ logits) {
    int t = blockIdx.x * blockDim.x + threadIdx.x;
    if (t < N_ * 24) {
        int n = t / 24, c = t % 24;
        g_op[n * S_OP + D_ + c] = (c < C_) ? logits[n * C_ + c] : 0.f;
    }
}

// ---------------- 3. softmax max prob + argmax ----------------
__global__ void softmax_kernel(const float* __restrict__ logits) {
    int i = blockIdx.x * blockDim.x + threadIdx.x;
    if (i >= N_) return;
    const float* l = logits + i * C_;
    float m = -INFINITY; int am = 0;
    #pragma unroll
    for (int c = 0; c < C_; c++) { float v = l[c]; if (v > m) { m = v; am = c; } }
    float s = 0.f;
    #pragma unroll
    for (int c = 0; c < C_; c++) s += expf(l[c] - m);
    g_maxlogit[i] = 1.0f / s;
    g_maxcls[i] = am;
}

// ---------------- 4a. prep: accepted index lists + closed-form weights ----------------
// sequential scan p_j = (p_{j-1}+x_j)/j  =>  p_m = sum_j x_j * (j-1)!/m!
__global__ void prep_kernel(const int* __restrict__ labels) {
    int t = threadIdx.x;
    if (t < 42) {
        int dom = t / C_, cls = t % C_;
        float thr = 0.1f; int m = 0;
        int* idx = g_pidx + t * NS_;
        for (int i = 0; i < NS_; i++) {
            int smp = dom * NS_ + i;
            if (g_maxcls[smp] == cls) {
                float ml = g_maxlogit[smp];
                if (ml >= thr) {
                    idx[m++] = smp;
                    thr = 0.5f * thr + 0.5f * ml;
                }
            }
        }
        g_pm[t] = m;
        float* w = g_pw + t * NS_;
        if (m > 0) {
            float wj = 1.0f / (float)m;
            for (int j = m - 1; j >= 0; --j) {
                w[j] = wj;
                if (j > 0) wj = wj / (float)j;
            }
        }
    } else if (t >= 64 && t < 64 + C_) {
        int cls = t - 64; int m = 0;
        int* idx = g_lidx + cls * NS_;
        for (int i = 0; i < NS_; i++) if (labels[i] == cls) idx[m++] = i;
        g_lm[cls] = m;
        g_counts[cls] = (float)m;
    }
}

// ---------------- 4b. parallel weighted proto gather ----------------
__global__ void proto_sum_kernel() {
    int pc = blockIdx.x;                       // 0..41 (dom*21+cls)
    int d = blockIdx.y * 256 + threadIdx.x;
    int m = g_pm[pc];
    const int* idx = g_pidx + pc * NS_;
    const float* w = g_pw + pc * NS_;
    float acc = 0.f;
    for (int j = 0; j < m; ++j) acc += w[j] * g_op[idx[j] * S_OP + d];
    g_protos[pc * D_ + d] = acc;
}

// ---------------- 5. bwl parallel gather ----------------
__global__ void bwl_sum_kernel() {
    int cls = blockIdx.x;
    int d = blockIdx.y * 256 + threadIdx.x;
    int m = g_lm[cls];
    const int* idx = g_lidx + cls * NS_;
    float s = 0.f;
    for (int j = 0; j < m; ++j) s += g_op[idx[j] * S_OP + d];
    g_bwl[cls * D_ + d] = (m > 0) ? (s / (float)m) : 0.f;
}

// ---------------- 6. row norms ----------------
__global__ void norms_kernel() {
    __shared__ float sh[256];
    int mat = blockIdx.x / C_;
    int r = blockIdx.x % C_;
    const float* p;
    if (mat == 0)      p = g_protos + (C_ + r) * D_;
    else if (mat == 1) p = g_protos + r * D_;
    else               p = g_bwl + r * D_;
    float s = 0.f;
    for (int d = threadIdx.x; d < D_; d += 256) { float v = p[d]; s += v * v; }
    s = block_reduce_256(s, sh);
    if (threadIdx.x == 0) g_norms[mat * C_ + r] = fmaxf(sqrtf(s), 1e-8f);
}

// ---------------- 7. cos maps + masked abs diff ----------------
__global__ void diff_kernel() {
    __shared__ float sh[256];
    int i = blockIdx.x / 20 + 1;
    int j = blockIdx.x % 20 + 1;
    const float* t = g_protos + (C_ + i) * D_;
    const float* s = g_protos + j * D_;
    const float* b = g_bwl + j * D_;
    float d1 = 0.f, d2 = 0.f;
    for (int d = threadIdx.x; d < D_; d += 256) {
        float tv = t[d];
        d1 += tv * s[d];
        d2 += tv * b[d];
    }
    d1 = block_reduce_256(d1, sh);
    d2 = block_reduce_256(d2, sh);
    if (threadIdx.x == 0) {
        float nt = g_norms[0 * C_ + i];
        float ns = g_norms[1 * C_ + j];
        float nb = g_norms[2 * C_ + j];
        float ptm = d1 / (nt * ns);
        float bw  = d2 / (nt * nb);
        float mask = (g_counts[i] > 0.f) ? 1.f : 0.f;
        g_diff[blockIdx.x] = fabsf(bw - ptm) * mask;
    }
}

// ---------------- 8. tf32 tensor-core GEMM, 128x128 block, split-K ----------------
// A row-major [M x lda], B row-major [K x 1024], Cpart[z] row-major [512 x 1024]
// 8 warps; warp tile 32x64 (2 mfrag x 8 nfrag of m16n8k8)
#define GBK 16
__global__ __launch_bounds__(256, 1)
void gemm_tf32_kernel(const float* __restrict__ A, int lda,
                      const float* __restrict__ B,
                      float* __restrict__ Cpart,
                      int Kreal, int Kpad, int kchunk) {
    __shared__ float As[2][128][20];
    __shared__ float Bs[2][GBK][136];

    const int tid = threadIdx.x;
    const int lane = tid & 31;
    const int gid = lane >> 2;
    const int tig = lane & 3;
    const int warpId = tid >> 5;
    const int warpM = warpId & 3;      // 0..3 -> 32-row slab
    const int warpN = warpId >> 2;     // 0..1 -> 64-col slab
    const int blockM = blockIdx.y * 128;
    const int blockN = blockIdx.x * 128;
    const int z = blockIdx.z;

    const int kbeg = z * kchunk;
    const int kend = min(kbeg + kchunk, Kpad);
    const int iters = (kend - kbeg + GBK - 1) / GBK;

    float acc[2][8][4];
    #pragma unroll
    for (int i = 0; i < 2; i++)
        #pragma unroll
        for (int j = 0; j < 8; j++)
            #pragma unroll
            for (int q = 0; q < 4; q++) acc[i][j][q] = 0.f;

    // stage loader
    auto load_stage = [&](int s, int k0) {
        // A: 128 rows x 16 cols = 512 x 16B ops
        #pragma unroll
        for (int r = 0; r < 2; r++) {
            int o = tid + r * 256;
            int m = o >> 2, kq = o & 3;
            int gk = k0 + kq * 4;
            bool p = (gk < Kpad);
            const float* src = p ? (A + (size_t)(blockM + m) * lda + gk) : A;
            cp_async16(&As[s][m][kq * 4], src, p);
        }
        // B: 16 rows x 128 cols = 512 x 16B ops
        #pragma unroll
        for (int r = 0; r < 2; r++) {
            int o = tid + r * 256;
            int kr = o >> 5, c4 = o & 31;
            bool p = (k0 + kr) < Kreal;
            const float* src = p ? (B + (size_t)(k0 + kr) * H1_ + blockN + c4 * 4) : B;
            cp_async16(&Bs[s][kr][c4 * 4], src, p);
        }
        cp_commit();
    };

    load_stage(0, kbeg);
    int buf = 0;
    for (int it = 0; it < iters; ++it) {
        if (it + 1 < iters) {
            load_stage(buf ^ 1, kbeg + (it + 1) * GBK);
            cp_wait<1>();
        } else {
            cp_wait<0>();
        }
        __syncthreads();

        #pragma unroll
        for (int kk = 0; kk < GBK; kk += 8) {
            uint32_t a[2][4], b[8][2];
            const int mrow = warpM * 32;
            #pragma unroll
            for (int i = 0; i < 2; i++) {
                int r0 = mrow + 16 * i + gid;
                a[i][0] = __float_as_uint(As[buf][r0][kk + tig]);
                a[i][1] = __float_as_uint(As[buf][r0 + 8][kk + tig]);
                a[i][2] = __float_as_uint(As[buf][r0][kk + tig + 4]);
                a[i][3] = __float_as_uint(As[buf][r0 + 8][kk + tig + 4]);
            }
            const int ncol = warpN * 64;
            #pragma unroll
            for (int j = 0; j < 8; j++) {
                b[j][0] = __float_as_uint(Bs[buf][kk + tig][ncol + 8 * j + gid]);
                b[j][1] = __float_as_uint(Bs[buf][kk + tig + 4][ncol + 8 * j + gid]);
            }
            #pragma unroll
            for (int i = 0; i < 2; i++)
                #pragma unroll
                for (int j = 0; j < 8; j++)
                    mma_tf32(acc[i][j], a[i], b[j]);
        }
        __syncthreads();
        buf ^= 1;
    }

    // epilogue -> partial buffer
    float* Cz = Cpart + (size_t)z * N_ * H1_;
    #pragma unroll
    for (int i = 0; i < 2; i++) {
        #pragma unroll
        for (int j = 0; j < 8; j++) {
            int row = blockM + warpM * 32 + 16 * i + gid;
            int col = blockN + warpN * 64 + 8 * j + 2 * tig;
            float2 v0 = make_float2(acc[i][j][0], acc[i][j][1]);
            float2 v1 = make_float2(acc[i][j][2], acc[i][j][3]);
            *(float2*)&Cz[(size_t)row * H1_ + col] = v0;
            *(float2*)&Cz[(size_t)(row + 8) * H1_ + col] = v1;
        }
    }
}

// ---------------- 9. splitK reduce + bias + layernorm + relu ----------------
__global__ void ln_relu_kernel(float* __restrict__ h, const float* __restrict__ bias) {
    __shared__ float sh[256];
    int row = blockIdx.x;
    float vals[4];
    float s = 0.f;
    #pragma unroll
    for (int k = 0; k < 4; k++) {
        int c = threadIdx.x + k * 256;
        size_t off = (size_t)row * H1_ + c;
        float v = g_part[off] + g_part[N_ * H1_ + off]
                + g_part[2 * N_ * H1_ + off] + g_part[3 * N_ * H1_ + off]
                + bias[c];
        vals[k] = v;
        s += v;
    }
    float tot = block_reduce_256(s, sh);
    float mu = tot * (1.0f / H1_);
    float v = 0.f;
    #pragma unroll
    for (int k = 0; k < 4; k++) { float dd = vals[k] - mu; v += dd * dd; }
    float vtot = block_reduce_256(v, sh);
    float inv = rsqrtf(vtot * (1.0f / H1_) + 1e-5f);
    #pragma unroll
    for (int k = 0; k < 4; k++) {
        int c = threadIdx.x + k * 256;
        float o = (vals[k] - mu) * inv;
        h[(size_t)row * H1_ + c] = o > 0.f ? o : 0.f;
    }
}

// ---------------- 10. gemv ----------------
__global__ void gemv_kernel(const float* __restrict__ h, const float* __restrict__ Wd,
                            const float* __restrict__ bd) {
    __shared__ float sh[256];
    int row = blockIdx.x;
    float s = 0.f;
    for (int c = threadIdx.x; c < H1_; c += 256) s += h[(size_t)row * H1_ + c] * Wd[c];
    s = block_reduce_256(s, sh);
    if (threadIdx.x == 0) g_z[row] = s + bd[0];
}

// ---------------- 11. final ----------------
__global__ void final_kernel(const int* __restrict__ dlabels, float* __restrict__ out) {
    __shared__ float red[512];
    int t = threadIdx.x;
    float p = 1.f / (1.f + expf(-g_z[t]));
    float y = (float)dlabels[t];
    float v = fmaxf(p, 0.f) - p * y + log1pf(expf(-fabsf(p)));
    red[t] = v; __syncthreads();
    #pragma unroll
    for (int s = 256; s > 0; s >>= 1) { if (t < s) red[t] += red[t + s]; __syncthreads(); }
    float loss_ea = red[0] * (1.0f / N_);
    __syncthreads();
    red[t] = (t < 400) ? g_diff[t] : 0.f; __syncthreads();
    #pragma unroll
    for (int s = 256; s > 0; s >>= 1) { if (t < s) red[t] += red[t + s]; __syncthreads(); }
    float dsum = red[0];
    __syncthreads();
    red[t] = (t >= 1 && t < C_) ? ((g_counts[t] > 0.f) ? 1.f : 0.f) : 0.f; __syncthreads();
    #pragma unroll
    for (int s = 256; s > 0; s >>= 1) { if (t < s) red[t] += red[t + s]; __syncthreads(); }
    if (t == 0) {
        float msum = red[0];
        out[0] = dsum / (msum * (float)(C_ - 1));
        out[1] = loss_ea;
    }
}

// ---------------- launch ----------------
extern "C" void kernel_launch(void* const* d_in, const int* in_sizes, int n_in,
                              void* d_out, int out_size) {
    const float* ins_features  = (const float*)d_in[0];
    const float* class_logits  = (const float*)d_in[1];
    const float* W1 = (const float*)d_in[2];
    const float* b1 = (const float*)d_in[3];
    const float* W2 = (const float*)d_in[4];
    const float* b2 = (const float*)d_in[5];
    const float* W3 = (const float*)d_in[6];
    const float* b3 = (const float*)d_in[7];
    const float* Wd = (const float*)d_in[8];
    const float* bd = (const float*)d_in[9];
    const int* labels        = (const int*)d_in[10];
    const int* domain_labels = (const int*)d_in[11];
    float* out = (float*)d_out;

    float* op   = nullptr; cudaGetSymbolAddress((void**)&op, g_op);
    float* bufA = nullptr; cudaGetSymbolAddress((void**)&bufA, g_bufA);
    float* bufB = nullptr; cudaGetSymbolAddress((void**)&bufB, g_bufB);
    float* part = nullptr; cudaGetSymbolAddress((void**)&part, g_part);

    pool_kernel<<<8192, 256>>>(ins_features);
    copy_logits_kernel<<<(N_ * 24 + 255) / 256, 256>>>(class_logits);
    softmax_kernel<<<2, 256>>>(class_logits);
    prep_kernel<<<1, 128>>>(labels);
    proto_sum_kernel<<<dim3(42, 8), 256>>>();
    bwl_sum_kernel<<<dim3(C_, 8), 256>>>();
    norms_kernel<<<3 * C_, 256>>>();
    diff_kernel<<<400, 256>>>();

    dim3 gg(H1_ / 128, N_ / 128, 4);   // (8,4,4) = 128 blocks
    // GEMM1: A = g_op [512 x 2072 padded], K real 2069
    gemm_tf32_kernel<<<gg, 256>>>(op, S_OP, W1, part, DIN_, S_OP, 528);
    ln_relu_kernel<<<N_, 256>>>(bufA, b1);
    gemm_tf32_kernel<<<gg, 256>>>(bufA, H1_, W2, part, H1_, H1_, 256);
    ln_relu_kernel<<<N_, 256>>>(bufB, b2);
    gemm_tf32_kernel<<<gg, 256>>>(bufB, H1_, W3, part, H1_, H1_, 256);
    ln_relu_kernel<<<N_, 256>>>(bufA, b3);
    gemv_kernel<<<N_, 256>>>(bufA, Wd, bd);

    final_kernel<<<1, 512>>>(domain_labels, out);
}